// round 4
// baseline (speedup 1.0000x reference)
#include <cuda_runtime.h>

#define N_USERS 100000
#define N_ITEMS 50000
#define N_NODES 150000
#define KDIM    64
#define N_EDGES 2000000
#define BATCH   4096
#define NEG_SLOPE 0.01f
#define EPSV    1e-12f

#define SCAN_ELEMS 4096
#define SCAN_BLOCKS ((N_NODES + SCAN_ELEMS - 1) / SCAN_ELEMS)   // 37

#define NPB   128                 // nodes per k_layer block
#define ROWP  130                 // smem row stride (floats), even + bank spread
#define LAYER_SMEM ((2 * 64 * ROWP + NPB) * 4)   // 67072 bytes

typedef unsigned long long u64;

__device__ __forceinline__ u64 dup2(float v) {
    u64 r; asm("mov.b64 %0, {%1, %1};" : "=l"(r) : "f"(v)); return r;
}
__device__ __forceinline__ u64 pack2(float lo, float hi) {
    u64 r; asm("mov.b64 %0, {%1, %2};" : "=l"(r) : "f"(lo), "f"(hi)); return r;
}
__device__ __forceinline__ float2 unpack2(u64 v) {
    float2 f; asm("mov.b64 {%0, %1}, %2;" : "=f"(f.x), "=f"(f.y) : "l"(v)); return f;
}
__device__ __forceinline__ void fma2(u64& d, u64 a, u64 b) {
    asm("fma.rn.f32x2 %0, %1, %2, %0;" : "+l"(d) : "l"(a), "l"(b));
}

// ---------------- scratch ----------------------------------------------------
__device__ float g_X[(size_t)N_NODES * KDIM];
__device__ float g_Y[(size_t)N_NODES * KDIM];
__device__ int   g_cnt[N_NODES];
__device__ int   g_off[N_NODES + 1];
__device__ int   g_fill[N_NODES];
__device__ int2  g_edge[N_EDGES];     // .x = src, .y = weight bits
__device__ int   g_part[SCAN_BLOCKS];
__device__ int   g_partoff[SCAN_BLOCKS];

// ---------------- init: X = concat(Gu, Gi); zero counters ------------------
__global__ void k_init(const float* __restrict__ Gu, const float* __restrict__ Gi) {
    int i = blockIdx.x * blockDim.x + threadIdx.x;
    const int total  = N_NODES * KDIM / 4;
    const int usplit = N_USERS * KDIM / 4;
    if (i < N_NODES) g_cnt[i] = 0;
    if (i >= total) return;
    float4 v = (i < usplit) ? ((const float4*)Gu)[i] : ((const float4*)Gi)[i - usplit];
    ((float4*)g_X)[i] = v;
}

// ---------------- CSR build -------------------------------------------------
__global__ void k_hist(const int* __restrict__ dst) {
    int e = blockIdx.x * blockDim.x + threadIdx.x;
    if (e >= N_EDGES) return;
    atomicAdd(&g_cnt[dst[e]], 1);
}

__global__ void __launch_bounds__(1024) k_part() {
    __shared__ int red[32];
    int tid = threadIdx.x;
    int base = blockIdx.x * SCAN_ELEMS + tid * 4;
    int s = 0;
#pragma unroll
    for (int j = 0; j < 4; j++) {
        int g = base + j;
        s += (g < N_NODES) ? g_cnt[g] : 0;
    }
#pragma unroll
    for (int o = 16; o; o >>= 1) s += __shfl_xor_sync(0xffffffffu, s, o);
    if ((tid & 31) == 0) red[tid >> 5] = s;
    __syncthreads();
    if (tid < 32) {
        int v = red[tid];
#pragma unroll
        for (int o = 16; o; o >>= 1) v += __shfl_xor_sync(0xffffffffu, v, o);
        if (tid == 0) g_part[blockIdx.x] = v;
    }
}

__global__ void k_scanpart() {
    __shared__ int s[64];
    int tid = threadIdx.x;
    int v = (tid < SCAN_BLOCKS) ? g_part[tid] : 0;
    s[tid] = v;
    __syncthreads();
#pragma unroll
    for (int o = 1; o < 64; o <<= 1) {
        int t = (tid >= o) ? s[tid - o] : 0;
        __syncthreads();
        s[tid] += t;
        __syncthreads();
    }
    if (tid < SCAN_BLOCKS) g_partoff[tid] = s[tid] - v;
    if (tid == 63) g_off[N_NODES] = s[63];
}

__global__ void __launch_bounds__(1024) k_scanfinal() {
    __shared__ int wsm[33];
    int tid = threadIdx.x;
    int lane = tid & 31, wid = tid >> 5;
    int base = blockIdx.x * SCAN_ELEMS + tid * 4;
    int v[4];
    int t = 0;
#pragma unroll
    for (int j = 0; j < 4; j++) {
        int g = base + j;
        v[j] = (g < N_NODES) ? g_cnt[g] : 0;
        t += v[j];
    }
    int inc = t;
#pragma unroll
    for (int o = 1; o < 32; o <<= 1) {
        int u = __shfl_up_sync(0xffffffffu, inc, o);
        if (lane >= o) inc += u;
    }
    if (lane == 31) wsm[wid] = inc;
    __syncthreads();
    if (wid == 0) {
        int w = wsm[lane];
        int wi = w;
#pragma unroll
        for (int o = 1; o < 32; o <<= 1) {
            int u = __shfl_up_sync(0xffffffffu, wi, o);
            if (lane >= o) wi += u;
        }
        wsm[lane] = wi - w;
    }
    __syncthreads();
    int excl = g_partoff[blockIdx.x] + wsm[wid] + inc - t;
#pragma unroll
    for (int j = 0; j < 4; j++) {
        int g = base + j;
        if (g < N_NODES) { g_off[g] = excl; g_fill[g] = excl; }
        excl += v[j];
    }
}

__global__ void k_fill(const int* __restrict__ src, const int* __restrict__ dst,
                       const float* __restrict__ ew) {
    int e = blockIdx.x * blockDim.x + threadIdx.x;
    if (e >= N_EDGES) return;
    int d = dst[e];
    int p = atomicAdd(&g_fill[d], 1);
    g_edge[p] = make_int2(src[e], __float_as_int(ew[e]));
}

// ---------------- fused layer: gather + GEMM + LeakyReLU + L2-norm ---------
// Phase 1 (4 warps, 32 nodes each): S[n] = sum w*x[src]; build transposed
//   smem tiles a=s+x, b=s*x (+ sW = sum w).
// Phase 2 (16 groups of 8 threads): out = a*W1 + b*W2 + (ws+1)*b1 + ws*b2,
//   LeakyReLU, row L2-normalize. Each thread owns 8 cols for 8 nodes (FFMA2).
__global__ void __launch_bounds__(128) k_layer(
    const float* __restrict__ W1, const float* __restrict__ b1,
    const float* __restrict__ W2, const float* __restrict__ b2,
    int l) {
    extern __shared__ float smem_dyn[];
    float* sA = smem_dyn;                 // [64][ROWP]
    float* sB = smem_dyn + 64 * ROWP;     // [64][ROWP]
    float* sW = smem_dyn + 2 * 64 * ROWP; // [NPB]

    const float* __restrict__ X  = (l & 1) ? g_Y : g_X;
    float* __restrict__ Yout     = (l & 1) ? g_X : g_Y;

    int tid = threadIdx.x;
    int wid = tid >> 5, lane = tid & 31;
    int node0 = blockIdx.x * NPB;

    // ---- phase 1: gather ----
    for (int m = 0; m < 32; m++) {
        int nl = wid * 32 + m;
        int n = node0 + nl;
        float ax = 0.0f, ay = 0.0f, wa = 0.0f;
        if (n < N_NODES) {
            int b = g_off[n], e = g_off[n + 1];
            int i = b;
            for (; i + 3 < e; i += 4) {
                int2 E0 = g_edge[i];
                int2 E1 = g_edge[i + 1];
                int2 E2 = g_edge[i + 2];
                int2 E3 = g_edge[i + 3];
                float2 v0 = *(const float2*)&X[(size_t)E0.x * KDIM + lane * 2];
                float2 v1 = *(const float2*)&X[(size_t)E1.x * KDIM + lane * 2];
                float2 v2 = *(const float2*)&X[(size_t)E2.x * KDIM + lane * 2];
                float2 v3 = *(const float2*)&X[(size_t)E3.x * KDIM + lane * 2];
                float w0 = __int_as_float(E0.y), w1 = __int_as_float(E1.y);
                float w2 = __int_as_float(E2.y), w3 = __int_as_float(E3.y);
                ax += w0 * v0.x + w1 * v1.x + w2 * v2.x + w3 * v3.x;
                ay += w0 * v0.y + w1 * v1.y + w2 * v2.y + w3 * v3.y;
                wa += w0 + w1 + w2 + w3;
            }
            for (; i < e; i++) {
                int2 E0 = g_edge[i];
                float w0 = __int_as_float(E0.y);
                float2 v0 = *(const float2*)&X[(size_t)E0.x * KDIM + lane * 2];
                ax += w0 * v0.x;
                ay += w0 * v0.y;
                wa += w0;
            }
            float2 xv = *(const float2*)&X[(size_t)n * KDIM + lane * 2];
            sA[(2 * lane + 0) * ROWP + nl] = ax + xv.x;
            sA[(2 * lane + 1) * ROWP + nl] = ay + xv.y;
            sB[(2 * lane + 0) * ROWP + nl] = ax * xv.x;
            sB[(2 * lane + 1) * ROWP + nl] = ay * xv.y;
        } else {
            sA[(2 * lane + 0) * ROWP + nl] = 0.0f;
            sA[(2 * lane + 1) * ROWP + nl] = 0.0f;
            sB[(2 * lane + 0) * ROWP + nl] = 0.0f;
            sB[(2 * lane + 1) * ROWP + nl] = 0.0f;
        }
        if (lane == 0) sW[nl] = wa;
    }
    __syncthreads();

    // ---- phase 2: update ----
    int g8 = tid >> 3;          // 0..15
    int t8 = tid & 7;
    int c  = t8 * 8;
    int nb = g8 * 8;

    const float* W1l = W1 + l * 4096;
    const float* W2l = W2 + l * 4096;
    float4 B1a = __ldg((const float4*)&b1[l * 64 + c]);
    float4 B1b = __ldg((const float4*)&b1[l * 64 + c + 4]);
    float4 B2a = __ldg((const float4*)&b2[l * 64 + c]);
    float4 B2b = __ldg((const float4*)&b2[l * 64 + c + 4]);
    float bv1[8] = {B1a.x, B1a.y, B1a.z, B1a.w, B1b.x, B1b.y, B1b.z, B1b.w};
    float bv2[8] = {B2a.x, B2a.y, B2a.z, B2a.w, B2b.x, B2b.y, B2b.z, B2b.w};

    u64 acc[4][8];
#pragma unroll
    for (int p = 0; p < 4; p++) {
        float w0 = sW[nb + 2 * p];
        float w1 = sW[nb + 2 * p + 1];
#pragma unroll
        for (int j = 0; j < 8; j++)
            acc[p][j] = pack2((w0 + 1.0f) * bv1[j] + w0 * bv2[j],
                              (w1 + 1.0f) * bv1[j] + w1 * bv2[j]);
    }

    for (int k = 0; k < 64; k++) {
        float4 wa1 = __ldg((const float4*)&W1l[k * 64 + c]);
        float4 wb1 = __ldg((const float4*)&W1l[k * 64 + c + 4]);
        float4 wa2 = __ldg((const float4*)&W2l[k * 64 + c]);
        float4 wb2 = __ldg((const float4*)&W2l[k * 64 + c + 4]);
        u64 d1[8], d2[8];
        d1[0] = dup2(wa1.x); d1[1] = dup2(wa1.y); d1[2] = dup2(wa1.z); d1[3] = dup2(wa1.w);
        d1[4] = dup2(wb1.x); d1[5] = dup2(wb1.y); d1[6] = dup2(wb1.z); d1[7] = dup2(wb1.w);
        d2[0] = dup2(wa2.x); d2[1] = dup2(wa2.y); d2[2] = dup2(wa2.z); d2[3] = dup2(wa2.w);
        d2[4] = dup2(wb2.x); d2[5] = dup2(wb2.y); d2[6] = dup2(wb2.z); d2[7] = dup2(wb2.w);
        const float* ra = &sA[k * ROWP + nb];
        const float* rb = &sB[k * ROWP + nb];
        u64 ap[4], bp[4];
#pragma unroll
        for (int p = 0; p < 4; p++) {
            ap[p] = *(const u64*)&ra[2 * p];
            bp[p] = *(const u64*)&rb[2 * p];
        }
#pragma unroll
        for (int p = 0; p < 4; p++) {
#pragma unroll
            for (int j = 0; j < 8; j++) fma2(acc[p][j], ap[p], d1[j]);
#pragma unroll
            for (int j = 0; j < 8; j++) fma2(acc[p][j], bp[p], d2[j]);
        }
    }

    // LeakyReLU + row L2 normalize (8-thread group reduce), store
#pragma unroll
    for (int p = 0; p < 4; p++) {
        float2 y[8];
#pragma unroll
        for (int j = 0; j < 8; j++) {
            float2 v = unpack2(acc[p][j]);
            y[j].x = v.x > 0.0f ? v.x : NEG_SLOPE * v.x;
            y[j].y = v.y > 0.0f ? v.y : NEG_SLOPE * v.y;
        }
        float ssx = 0.0f, ssy = 0.0f;
#pragma unroll
        for (int j = 0; j < 8; j++) { ssx += y[j].x * y[j].x; ssy += y[j].y * y[j].y; }
#pragma unroll
        for (int o = 1; o < 8; o <<= 1) {
            ssx += __shfl_xor_sync(0xffffffffu, ssx, o);
            ssy += __shfl_xor_sync(0xffffffffu, ssy, o);
        }
        float inv0 = 1.0f / fmaxf(sqrtf(ssx), EPSV);
        float inv1 = 1.0f / fmaxf(sqrtf(ssy), EPSV);
        int n0 = node0 + nb + 2 * p;
        if (n0 < N_NODES) {
            *(float4*)&Yout[(size_t)n0 * KDIM + c] =
                make_float4(y[0].x * inv0, y[1].x * inv0, y[2].x * inv0, y[3].x * inv0);
            *(float4*)&Yout[(size_t)n0 * KDIM + c + 4] =
                make_float4(y[4].x * inv0, y[5].x * inv0, y[6].x * inv0, y[7].x * inv0);
        }
        if (n0 + 1 < N_NODES) {
            *(float4*)&Yout[(size_t)(n0 + 1) * KDIM + c] =
                make_float4(y[0].y * inv1, y[1].y * inv1, y[2].y * inv1, y[3].y * inv1);
            *(float4*)&Yout[(size_t)(n0 + 1) * KDIM + c + 4] =
                make_float4(y[4].y * inv1, y[5].y * inv1, y[6].y * inv1, y[7].y * inv1);
        }
    }
}

// ---------------- incremental batch dot ------------------------------------
__global__ void k_dot(const int* __restrict__ user, const int* __restrict__ pos,
                      float* __restrict__ out, int sel, int first) {
    const float* __restrict__ X = sel ? g_Y : g_X;
    int gthr = blockIdx.x * blockDim.x + threadIdx.x;
    int w = gthr >> 5;
    if (w >= BATCH) return;
    int lane = threadIdx.x & 31;
    int u  = user[w];
    int it = pos[w];
    float2 a = *(const float2*)&X[(size_t)u * KDIM + lane * 2];
    float2 b = *(const float2*)&X[((size_t)N_USERS + it) * KDIM + lane * 2];
    float d = a.x * b.x + a.y * b.y;
    d += __shfl_xor_sync(0xffffffffu, d, 16);
    d += __shfl_xor_sync(0xffffffffu, d, 8);
    d += __shfl_xor_sync(0xffffffffu, d, 4);
    d += __shfl_xor_sync(0xffffffffu, d, 2);
    d += __shfl_xor_sync(0xffffffffu, d, 1);
    if (lane == 0) out[w] = first ? d : out[w] + d;
}

// ---------------- launch ----------------------------------------------------
extern "C" void kernel_launch(void* const* d_in, const int* in_sizes, int n_in,
                              void* d_out, int out_size) {
    const float* Gu   = (const float*)d_in[0];
    const float* Gi   = (const float*)d_in[1];
    const float* W1   = (const float*)d_in[2];
    const float* b1   = (const float*)d_in[3];
    const float* W2   = (const float*)d_in[4];
    const float* b2   = (const float*)d_in[5];
    const float* ew   = (const float*)d_in[6];
    const int*   esrc = (const int*)d_in[7];
    const int*   edst = (const int*)d_in[8];
    const int*   user = (const int*)d_in[9];
    const int*   pos  = (const int*)d_in[10];
    float* out = (float*)d_out;

    cudaFuncSetAttribute(k_layer, cudaFuncAttributeMaxDynamicSharedMemorySize,
                         LAYER_SMEM);

    const int TB = 256;
    k_init<<<(N_NODES * KDIM / 4 + TB - 1) / TB, TB>>>(Gu, Gi);
    k_hist<<<(N_EDGES + TB - 1) / TB, TB>>>(edst);
    k_part<<<SCAN_BLOCKS, 1024>>>();
    k_scanpart<<<1, 64>>>();
    k_scanfinal<<<SCAN_BLOCKS, 1024>>>();
    k_fill<<<(N_EDGES + TB - 1) / TB, TB>>>(esrc, edst, ew);

    k_dot<<<(BATCH * 32 + TB - 1) / TB, TB>>>(user, pos, out, /*sel=*/0, /*first=*/1);

    for (int l = 0; l < 3; l++) {
        k_layer<<<(N_NODES + NPB - 1) / NPB, 128, LAYER_SMEM>>>(W1, b1, W2, b2, l);
        k_dot<<<(BATCH * 32 + TB - 1) / TB, TB>>>(user, pos, out, (l & 1) ^ 1, /*first=*/0);
    }
}

// round 5
// speedup vs baseline: 1.8537x; 1.8537x over previous
#include <cuda_runtime.h>

#define N_USERS 100000
#define N_ITEMS 50000
#define N_NODES 150000
#define KDIM    64
#define N_EDGES 2000000
#define BATCH   4096
#define NEG_SLOPE 0.01f
#define EPSV    1e-12f

#define SCAN_ELEMS 4096
#define SCAN_BLOCKS ((N_NODES + SCAN_ELEMS - 1) / SCAN_ELEMS)   // 37

#define NPB   128                 // nodes per k_update block
#define ROWP  130                 // smem row stride (floats)
#define UPD_SMEM (2 * 64 * ROWP * 4)   // 66560 bytes

typedef unsigned long long u64;

__device__ __forceinline__ u64 dup2(float v) {
    u64 r; asm("mov.b64 %0, {%1, %1};" : "=l"(r) : "f"(v)); return r;
}
__device__ __forceinline__ u64 pack2(float lo, float hi) {
    u64 r; asm("mov.b64 %0, {%1, %2};" : "=l"(r) : "f"(lo), "f"(hi)); return r;
}
__device__ __forceinline__ float2 unpack2(u64 v) {
    float2 f; asm("mov.b64 {%0, %1}, %2;" : "=f"(f.x), "=f"(f.y) : "l"(v)); return f;
}
__device__ __forceinline__ void fma2(u64& d, u64 a, u64 b) {
    asm("fma.rn.f32x2 %0, %1, %2, %0;" : "+l"(d) : "l"(a), "l"(b));
}

// ---------------- scratch ----------------------------------------------------
__device__ float g_X[(size_t)N_NODES * KDIM];
__device__ float g_Y[(size_t)N_NODES * KDIM];
__device__ float g_S[(size_t)N_NODES * KDIM];
__device__ float g_wsum[N_NODES];
__device__ int   g_cnt[N_NODES];
__device__ int   g_off[N_NODES + 1];
__device__ int   g_fill[N_NODES];
__device__ int2  g_edge[N_EDGES];     // .x = src, .y = weight bits
__device__ int   g_part[SCAN_BLOCKS];
__device__ int   g_partoff[SCAN_BLOCKS];

// ---------------- init: X = concat(Gu, Gi); zero counters ------------------
__global__ void k_init(const float* __restrict__ Gu, const float* __restrict__ Gi) {
    int i = blockIdx.x * blockDim.x + threadIdx.x;
    const int total  = N_NODES * KDIM / 4;
    const int usplit = N_USERS * KDIM / 4;
    if (i < N_NODES) g_cnt[i] = 0;
    if (i >= total) return;
    float4 v = (i < usplit) ? ((const float4*)Gu)[i] : ((const float4*)Gi)[i - usplit];
    ((float4*)g_X)[i] = v;
}

// ---------------- CSR build -------------------------------------------------
__global__ void k_hist(const int* __restrict__ dst) {
    int e = blockIdx.x * blockDim.x + threadIdx.x;
    if (e >= N_EDGES) return;
    atomicAdd(&g_cnt[dst[e]], 1);
}

__global__ void __launch_bounds__(1024) k_part() {
    __shared__ int red[32];
    int tid = threadIdx.x;
    int base = blockIdx.x * SCAN_ELEMS + tid * 4;
    int s = 0;
#pragma unroll
    for (int j = 0; j < 4; j++) {
        int g = base + j;
        s += (g < N_NODES) ? g_cnt[g] : 0;
    }
#pragma unroll
    for (int o = 16; o; o >>= 1) s += __shfl_xor_sync(0xffffffffu, s, o);
    if ((tid & 31) == 0) red[tid >> 5] = s;
    __syncthreads();
    if (tid < 32) {
        int v = red[tid];
#pragma unroll
        for (int o = 16; o; o >>= 1) v += __shfl_xor_sync(0xffffffffu, v, o);
        if (tid == 0) g_part[blockIdx.x] = v;
    }
}

__global__ void k_scanpart() {
    __shared__ int s[64];
    int tid = threadIdx.x;
    int v = (tid < SCAN_BLOCKS) ? g_part[tid] : 0;
    s[tid] = v;
    __syncthreads();
#pragma unroll
    for (int o = 1; o < 64; o <<= 1) {
        int t = (tid >= o) ? s[tid - o] : 0;
        __syncthreads();
        s[tid] += t;
        __syncthreads();
    }
    if (tid < SCAN_BLOCKS) g_partoff[tid] = s[tid] - v;
    if (tid == 63) g_off[N_NODES] = s[63];
}

__global__ void __launch_bounds__(1024) k_scanfinal() {
    __shared__ int wsm[33];
    int tid = threadIdx.x;
    int lane = tid & 31, wid = tid >> 5;
    int base = blockIdx.x * SCAN_ELEMS + tid * 4;
    int v[4];
    int t = 0;
#pragma unroll
    for (int j = 0; j < 4; j++) {
        int g = base + j;
        v[j] = (g < N_NODES) ? g_cnt[g] : 0;
        t += v[j];
    }
    int inc = t;
#pragma unroll
    for (int o = 1; o < 32; o <<= 1) {
        int u = __shfl_up_sync(0xffffffffu, inc, o);
        if (lane >= o) inc += u;
    }
    if (lane == 31) wsm[wid] = inc;
    __syncthreads();
    if (wid == 0) {
        int w = wsm[lane];
        int wi = w;
#pragma unroll
        for (int o = 1; o < 32; o <<= 1) {
            int u = __shfl_up_sync(0xffffffffu, wi, o);
            if (lane >= o) wi += u;
        }
        wsm[lane] = wi - w;
    }
    __syncthreads();
    int excl = g_partoff[blockIdx.x] + wsm[wid] + inc - t;
#pragma unroll
    for (int j = 0; j < 4; j++) {
        int g = base + j;
        if (g < N_NODES) { g_off[g] = excl; g_fill[g] = excl; }
        excl += v[j];
    }
}

__global__ void k_fill(const int* __restrict__ src, const int* __restrict__ dst,
                       const float* __restrict__ ew) {
    int e = blockIdx.x * blockDim.x + threadIdx.x;
    if (e >= N_EDGES) return;
    int d = dst[e];
    int p = atomicAdd(&g_fill[d], 1);
    g_edge[p] = make_int2(src[e], __float_as_int(ew[e]));
}

// ---------------- per-layer: S[n] = sum_e w_e * x[src_e]; wsum[n] = sum w --
__global__ void k_gather(int insel) {
    const float* __restrict__ X = insel ? g_Y : g_X;
    int gthr = blockIdx.x * blockDim.x + threadIdx.x;
    int n = gthr >> 5;
    if (n >= N_NODES) return;
    int lane = threadIdx.x & 31;
    int b = g_off[n], e = g_off[n + 1];
    float ax = 0.0f, ay = 0.0f, wa = 0.0f;
    int i = b;
    for (; i + 1 < e; i += 2) {
        int2 e0 = g_edge[i];
        int2 e1 = g_edge[i + 1];
        float w0 = __int_as_float(e0.y), w1 = __int_as_float(e1.y);
        float2 v0 = *(const float2*)&X[(size_t)e0.x * KDIM + lane * 2];
        float2 v1 = *(const float2*)&X[(size_t)e1.x * KDIM + lane * 2];
        ax += w0 * v0.x + w1 * v1.x;
        ay += w0 * v0.y + w1 * v1.y;
        wa += w0 + w1;
    }
    if (i < e) {
        int2 e0 = g_edge[i];
        float w0 = __int_as_float(e0.y);
        float2 v0 = *(const float2*)&X[(size_t)e0.x * KDIM + lane * 2];
        ax += w0 * v0.x;
        ay += w0 * v0.y;
        wa += w0;
    }
    *(float2*)&g_S[(size_t)n * KDIM + lane * 2] = make_float2(ax, ay);
    if (insel == 0 && lane == 0) g_wsum[n] = wa;
}

// ---------------- per-layer: GEMM + bias + LeakyReLU + L2-normalize --------
// 128 threads; stage 128 nodes transposed in smem; compute with 16 groups of
// 8 threads: each thread owns 8 cols for 8 nodes (4 f32x2 pairs), FFMA2 inner.
__global__ void __launch_bounds__(128) k_update(
    const float* __restrict__ W1, const float* __restrict__ b1,
    const float* __restrict__ W2, const float* __restrict__ b2,
    int l) {
    extern __shared__ float smem_dyn[];
    float* sA = smem_dyn;               // [64][ROWP] : a = s + x
    float* sB = smem_dyn + 64 * ROWP;   // [64][ROWP] : b = s * x
    const float* __restrict__ Xin = (l & 1) ? g_Y : g_X;
    float* __restrict__ Yout      = (l & 1) ? g_X : g_Y;

    int tid = threadIdx.x;
    int node0 = blockIdx.x * NPB;
    int grp = tid >> 4;        // 0..7, stages 8 nodes per pass
    int t16 = tid & 15;
    int cs  = t16 * 4;

    // stage two passes of 64 nodes each
#pragma unroll
    for (int pass = 0; pass < 2; pass++) {
#pragma unroll
        for (int m = 0; m < 8; m++) {
            int nl = pass * 64 + grp * 8 + m;
            int n = node0 + nl;
            if (n < N_NODES) {
                float4 sv = *(const float4*)&g_S[(size_t)n * KDIM + cs];
                float4 xv = *(const float4*)&Xin[(size_t)n * KDIM + cs];
                sA[(cs + 0) * ROWP + nl] = sv.x + xv.x;
                sA[(cs + 1) * ROWP + nl] = sv.y + xv.y;
                sA[(cs + 2) * ROWP + nl] = sv.z + xv.z;
                sA[(cs + 3) * ROWP + nl] = sv.w + xv.w;
                sB[(cs + 0) * ROWP + nl] = sv.x * xv.x;
                sB[(cs + 1) * ROWP + nl] = sv.y * xv.y;
                sB[(cs + 2) * ROWP + nl] = sv.z * xv.z;
                sB[(cs + 3) * ROWP + nl] = sv.w * xv.w;
            } else {
                sA[(cs + 0) * ROWP + nl] = 0.0f;
                sA[(cs + 1) * ROWP + nl] = 0.0f;
                sA[(cs + 2) * ROWP + nl] = 0.0f;
                sA[(cs + 3) * ROWP + nl] = 0.0f;
                sB[(cs + 0) * ROWP + nl] = 0.0f;
                sB[(cs + 1) * ROWP + nl] = 0.0f;
                sB[(cs + 2) * ROWP + nl] = 0.0f;
                sB[(cs + 3) * ROWP + nl] = 0.0f;
            }
        }
    }
    __syncthreads();

    int g8 = tid >> 3;          // 0..15
    int t8 = tid & 7;
    int c  = t8 * 8;
    int nb = g8 * 8;

    const float* W1l = W1 + l * 4096;
    const float* W2l = W2 + l * 4096;
    float4 B1a = __ldg((const float4*)&b1[l * 64 + c]);
    float4 B1b = __ldg((const float4*)&b1[l * 64 + c + 4]);
    float4 B2a = __ldg((const float4*)&b2[l * 64 + c]);
    float4 B2b = __ldg((const float4*)&b2[l * 64 + c + 4]);
    float bv1[8] = {B1a.x, B1a.y, B1a.z, B1a.w, B1b.x, B1b.y, B1b.z, B1b.w};
    float bv2[8] = {B2a.x, B2a.y, B2a.z, B2a.w, B2b.x, B2b.y, B2b.z, B2b.w};

    u64 acc[4][8];
#pragma unroll
    for (int p = 0; p < 4; p++) {
        int n0 = node0 + nb + 2 * p;
        float w0 = (n0 < N_NODES) ? g_wsum[n0] : 0.0f;
        float w1 = (n0 + 1 < N_NODES) ? g_wsum[n0 + 1] : 0.0f;
#pragma unroll
        for (int j = 0; j < 8; j++)
            acc[p][j] = pack2((w0 + 1.0f) * bv1[j] + w0 * bv2[j],
                              (w1 + 1.0f) * bv1[j] + w1 * bv2[j]);
    }

    for (int k = 0; k < 64; k++) {
        float4 wa1 = __ldg((const float4*)&W1l[k * 64 + c]);
        float4 wb1 = __ldg((const float4*)&W1l[k * 64 + c + 4]);
        float4 wa2 = __ldg((const float4*)&W2l[k * 64 + c]);
        float4 wb2 = __ldg((const float4*)&W2l[k * 64 + c + 4]);
        u64 d1[8], d2[8];
        d1[0] = dup2(wa1.x); d1[1] = dup2(wa1.y); d1[2] = dup2(wa1.z); d1[3] = dup2(wa1.w);
        d1[4] = dup2(wb1.x); d1[5] = dup2(wb1.y); d1[6] = dup2(wb1.z); d1[7] = dup2(wb1.w);
        d2[0] = dup2(wa2.x); d2[1] = dup2(wa2.y); d2[2] = dup2(wa2.z); d2[3] = dup2(wa2.w);
        d2[4] = dup2(wb2.x); d2[5] = dup2(wb2.y); d2[6] = dup2(wb2.z); d2[7] = dup2(wb2.w);
        const float* ra = &sA[k * ROWP + nb];
        const float* rb = &sB[k * ROWP + nb];
        u64 ap[4], bp[4];
#pragma unroll
        for (int p = 0; p < 4; p++) {
            ap[p] = *(const u64*)&ra[2 * p];
            bp[p] = *(const u64*)&rb[2 * p];
        }
#pragma unroll
        for (int p = 0; p < 4; p++) {
#pragma unroll
            for (int j = 0; j < 8; j++) fma2(acc[p][j], ap[p], d1[j]);
#pragma unroll
            for (int j = 0; j < 8; j++) fma2(acc[p][j], bp[p], d2[j]);
        }
    }

#pragma unroll
    for (int p = 0; p < 4; p++) {
        float2 y[8];
#pragma unroll
        for (int j = 0; j < 8; j++) {
            float2 v = unpack2(acc[p][j]);
            y[j].x = v.x > 0.0f ? v.x : NEG_SLOPE * v.x;
            y[j].y = v.y > 0.0f ? v.y : NEG_SLOPE * v.y;
        }
        float ssx = 0.0f, ssy = 0.0f;
#pragma unroll
        for (int j = 0; j < 8; j++) { ssx += y[j].x * y[j].x; ssy += y[j].y * y[j].y; }
#pragma unroll
        for (int o = 1; o < 8; o <<= 1) {
            ssx += __shfl_xor_sync(0xffffffffu, ssx, o);
            ssy += __shfl_xor_sync(0xffffffffu, ssy, o);
        }
        float inv0 = 1.0f / fmaxf(sqrtf(ssx), EPSV);
        float inv1 = 1.0f / fmaxf(sqrtf(ssy), EPSV);
        int n0 = node0 + nb + 2 * p;
        if (n0 < N_NODES) {
            *(float4*)&Yout[(size_t)n0 * KDIM + c] =
                make_float4(y[0].x * inv0, y[1].x * inv0, y[2].x * inv0, y[3].x * inv0);
            *(float4*)&Yout[(size_t)n0 * KDIM + c + 4] =
                make_float4(y[4].x * inv0, y[5].x * inv0, y[6].x * inv0, y[7].x * inv0);
        }
        if (n0 + 1 < N_NODES) {
            *(float4*)&Yout[(size_t)(n0 + 1) * KDIM + c] =
                make_float4(y[0].y * inv1, y[1].y * inv1, y[2].y * inv1, y[3].y * inv1);
            *(float4*)&Yout[(size_t)(n0 + 1) * KDIM + c + 4] =
                make_float4(y[4].y * inv1, y[5].y * inv1, y[6].y * inv1, y[7].y * inv1);
        }
    }
}

// ---------------- incremental batch dot ------------------------------------
__global__ void k_dot(const int* __restrict__ user, const int* __restrict__ pos,
                      float* __restrict__ out, int sel, int first) {
    const float* __restrict__ X = sel ? g_Y : g_X;
    int gthr = blockIdx.x * blockDim.x + threadIdx.x;
    int w = gthr >> 5;
    if (w >= BATCH) return;
    int lane = threadIdx.x & 31;
    int u  = user[w];
    int it = pos[w];
    float2 a = *(const float2*)&X[(size_t)u * KDIM + lane * 2];
    float2 b = *(const float2*)&X[((size_t)N_USERS + it) * KDIM + lane * 2];
    float d = a.x * b.x + a.y * b.y;
    d += __shfl_xor_sync(0xffffffffu, d, 16);
    d += __shfl_xor_sync(0xffffffffu, d, 8);
    d += __shfl_xor_sync(0xffffffffu, d, 4);
    d += __shfl_xor_sync(0xffffffffu, d, 2);
    d += __shfl_xor_sync(0xffffffffu, d, 1);
    if (lane == 0) out[w] = first ? d : out[w] + d;
}

// ---------------- launch ----------------------------------------------------
extern "C" void kernel_launch(void* const* d_in, const int* in_sizes, int n_in,
                              void* d_out, int out_size) {
    const float* Gu   = (const float*)d_in[0];
    const float* Gi   = (const float*)d_in[1];
    const float* W1   = (const float*)d_in[2];
    const float* b1   = (const float*)d_in[3];
    const float* W2   = (const float*)d_in[4];
    const float* b2   = (const float*)d_in[5];
    const float* ew   = (const float*)d_in[6];
    const int*   esrc = (const int*)d_in[7];
    const int*   edst = (const int*)d_in[8];
    const int*   user = (const int*)d_in[9];
    const int*   pos  = (const int*)d_in[10];
    float* out = (float*)d_out;

    cudaFuncSetAttribute(k_update, cudaFuncAttributeMaxDynamicSharedMemorySize,
                         UPD_SMEM);

    const int TB = 256;
    k_init<<<(N_NODES * KDIM / 4 + TB - 1) / TB, TB>>>(Gu, Gi);
    k_hist<<<(N_EDGES + TB - 1) / TB, TB>>>(edst);
    k_part<<<SCAN_BLOCKS, 1024>>>();
    k_scanpart<<<1, 64>>>();
    k_scanfinal<<<SCAN_BLOCKS, 1024>>>();
    k_fill<<<(N_EDGES + TB - 1) / TB, TB>>>(esrc, edst, ew);

    k_dot<<<(BATCH * 32 + TB - 1) / TB, TB>>>(user, pos, out, /*sel=*/0, /*first=*/1);

    for (int l = 0; l < 3; l++) {
        int insel  = l & 1;
        int outsel = insel ^ 1;
        k_gather<<<(N_NODES * 32 + TB - 1) / TB, TB>>>(insel);
        k_update<<<(N_NODES + NPB - 1) / NPB, 128, UPD_SMEM>>>(W1, b1, W2, b2, l);
        k_dot<<<(BATCH * 32 + TB - 1) / TB, TB>>>(user, pos, out, outsel, /*first=*/0);
    }
}

// round 6
// speedup vs baseline: 2.0743x; 1.1190x over previous
#include <cuda_runtime.h>

#define N_USERS 100000
#define N_ITEMS 50000
#define N_NODES 150000
#define KDIM    64
#define N_EDGES 2000000
#define BATCH   4096
#define NEG_SLOPE 0.01f
#define EPSV    1e-12f

#define SCAN_ELEMS 4096
#define SCAN_BLOCKS ((N_NODES + SCAN_ELEMS - 1) / SCAN_ELEMS)   // 37

typedef unsigned long long u64;

__device__ __forceinline__ u64 dup2(float v) {
    u64 r; asm("mov.b64 %0, {%1, %1};" : "=l"(r) : "f"(v)); return r;
}
__device__ __forceinline__ u64 pack2(float lo, float hi) {
    u64 r; asm("mov.b64 %0, {%1, %2};" : "=l"(r) : "f"(lo), "f"(hi)); return r;
}
__device__ __forceinline__ float2 unpack2(u64 v) {
    float2 f; asm("mov.b64 {%0, %1}, %2;" : "=f"(f.x), "=f"(f.y) : "l"(v)); return f;
}
__device__ __forceinline__ void fma2(u64& d, u64 a, u64 b) {
    asm("fma.rn.f32x2 %0, %1, %2, %0;" : "+l"(d) : "l"(a), "l"(b));
}

// ---------------- scratch ----------------------------------------------------
__device__ float g_X[(size_t)N_NODES * KDIM];
__device__ float g_Y[(size_t)N_NODES * KDIM];
__device__ float g_S[(size_t)N_NODES * KDIM];
__device__ float g_wsum[N_NODES];
__device__ int   g_cnt[N_NODES];
__device__ int   g_off[N_NODES + 1];
__device__ int   g_fill[N_NODES];
__device__ int2  g_edge[N_EDGES];     // .x = src, .y = weight bits
__device__ int   g_part[SCAN_BLOCKS];
__device__ int   g_partoff[SCAN_BLOCKS];

// ---------------- init: X = concat(Gu, Gi); zero counters ------------------
__global__ void k_init(const float* __restrict__ Gu, const float* __restrict__ Gi) {
    int i = blockIdx.x * blockDim.x + threadIdx.x;
    const int total  = N_NODES * KDIM / 4;
    const int usplit = N_USERS * KDIM / 4;
    if (i < N_NODES) g_cnt[i] = 0;
    if (i >= total) return;
    float4 v = (i < usplit) ? ((const float4*)Gu)[i] : ((const float4*)Gi)[i - usplit];
    ((float4*)g_X)[i] = v;
}

// ---------------- CSR build -------------------------------------------------
// 4 edges per thread, vectorized loads
__global__ void k_hist(const int* __restrict__ dst) {
    int t = blockIdx.x * blockDim.x + threadIdx.x;
    int e = t * 4;
    if (e + 3 < N_EDGES) {
        int4 d4 = *(const int4*)&dst[e];
        atomicAdd(&g_cnt[d4.x], 1);
        atomicAdd(&g_cnt[d4.y], 1);
        atomicAdd(&g_cnt[d4.z], 1);
        atomicAdd(&g_cnt[d4.w], 1);
    } else {
        for (int i = e; i < N_EDGES; i++) atomicAdd(&g_cnt[dst[i]], 1);
    }
}

__global__ void __launch_bounds__(1024) k_part() {
    __shared__ int red[32];
    int tid = threadIdx.x;
    int base = blockIdx.x * SCAN_ELEMS + tid * 4;
    int s = 0;
#pragma unroll
    for (int j = 0; j < 4; j++) {
        int g = base + j;
        s += (g < N_NODES) ? g_cnt[g] : 0;
    }
#pragma unroll
    for (int o = 16; o; o >>= 1) s += __shfl_xor_sync(0xffffffffu, s, o);
    if ((tid & 31) == 0) red[tid >> 5] = s;
    __syncthreads();
    if (tid < 32) {
        int v = red[tid];
#pragma unroll
        for (int o = 16; o; o >>= 1) v += __shfl_xor_sync(0xffffffffu, v, o);
        if (tid == 0) g_part[blockIdx.x] = v;
    }
}

__global__ void k_scanpart() {
    __shared__ int s[64];
    int tid = threadIdx.x;
    int v = (tid < SCAN_BLOCKS) ? g_part[tid] : 0;
    s[tid] = v;
    __syncthreads();
#pragma unroll
    for (int o = 1; o < 64; o <<= 1) {
        int t = (tid >= o) ? s[tid - o] : 0;
        __syncthreads();
        s[tid] += t;
        __syncthreads();
    }
    if (tid < SCAN_BLOCKS) g_partoff[tid] = s[tid] - v;
    if (tid == 63) g_off[N_NODES] = s[63];
}

__global__ void __launch_bounds__(1024) k_scanfinal() {
    __shared__ int wsm[33];
    int tid = threadIdx.x;
    int lane = tid & 31, wid = tid >> 5;
    int base = blockIdx.x * SCAN_ELEMS + tid * 4;
    int v[4];
    int t = 0;
#pragma unroll
    for (int j = 0; j < 4; j++) {
        int g = base + j;
        v[j] = (g < N_NODES) ? g_cnt[g] : 0;
        t += v[j];
    }
    int inc = t;
#pragma unroll
    for (int o = 1; o < 32; o <<= 1) {
        int u = __shfl_up_sync(0xffffffffu, inc, o);
        if (lane >= o) inc += u;
    }
    if (lane == 31) wsm[wid] = inc;
    __syncthreads();
    if (wid == 0) {
        int w = wsm[lane];
        int wi = w;
#pragma unroll
        for (int o = 1; o < 32; o <<= 1) {
            int u = __shfl_up_sync(0xffffffffu, wi, o);
            if (lane >= o) wi += u;
        }
        wsm[lane] = wi - w;
    }
    __syncthreads();
    int excl = g_partoff[blockIdx.x] + wsm[wid] + inc - t;
#pragma unroll
    for (int j = 0; j < 4; j++) {
        int g = base + j;
        if (g < N_NODES) { g_off[g] = excl; g_fill[g] = excl; }
        excl += v[j];
    }
}

__global__ void k_fill(const int* __restrict__ src, const int* __restrict__ dst,
                       const float* __restrict__ ew) {
    int t = blockIdx.x * blockDim.x + threadIdx.x;
    int e = t * 4;
    if (e + 3 < N_EDGES) {
        int4   s4 = *(const int4*)&src[e];
        int4   d4 = *(const int4*)&dst[e];
        float4 w4 = *(const float4*)&ew[e];
        int p0 = atomicAdd(&g_fill[d4.x], 1);
        int p1 = atomicAdd(&g_fill[d4.y], 1);
        int p2 = atomicAdd(&g_fill[d4.z], 1);
        int p3 = atomicAdd(&g_fill[d4.w], 1);
        g_edge[p0] = make_int2(s4.x, __float_as_int(w4.x));
        g_edge[p1] = make_int2(s4.y, __float_as_int(w4.y));
        g_edge[p2] = make_int2(s4.z, __float_as_int(w4.z));
        g_edge[p3] = make_int2(s4.w, __float_as_int(w4.w));
    } else {
        for (int i = e; i < N_EDGES; i++) {
            int p = atomicAdd(&g_fill[dst[i]], 1);
            g_edge[p] = make_int2(src[i], __float_as_int(ew[i]));
        }
    }
}

// ---------------- per-layer: S[n] = sum_e w_e * x[src_e]; wsum[n] = sum w --
__global__ void k_gather(int insel) {
    const float* __restrict__ X = insel ? g_Y : g_X;
    int gthr = blockIdx.x * blockDim.x + threadIdx.x;
    int n = gthr >> 5;
    if (n >= N_NODES) return;
    int lane = threadIdx.x & 31;
    int b = g_off[n], e = g_off[n + 1];
    float ax = 0.0f, ay = 0.0f, wa = 0.0f;
    int i = b;
    for (; i + 3 < e; i += 4) {
        int2 E0 = g_edge[i];
        int2 E1 = g_edge[i + 1];
        int2 E2 = g_edge[i + 2];
        int2 E3 = g_edge[i + 3];
        float2 v0 = *(const float2*)&X[(size_t)E0.x * KDIM + lane * 2];
        float2 v1 = *(const float2*)&X[(size_t)E1.x * KDIM + lane * 2];
        float2 v2 = *(const float2*)&X[(size_t)E2.x * KDIM + lane * 2];
        float2 v3 = *(const float2*)&X[(size_t)E3.x * KDIM + lane * 2];
        float w0 = __int_as_float(E0.y), w1 = __int_as_float(E1.y);
        float w2 = __int_as_float(E2.y), w3 = __int_as_float(E3.y);
        ax += w0 * v0.x + w1 * v1.x + w2 * v2.x + w3 * v3.x;
        ay += w0 * v0.y + w1 * v1.y + w2 * v2.y + w3 * v3.y;
        wa += w0 + w1 + w2 + w3;
    }
    for (; i < e; i++) {
        int2 E0 = g_edge[i];
        float w0 = __int_as_float(E0.y);
        float2 v0 = *(const float2*)&X[(size_t)E0.x * KDIM + lane * 2];
        ax += w0 * v0.x;
        ay += w0 * v0.y;
        wa += w0;
    }
    *(float2*)&g_S[(size_t)n * KDIM + lane * 2] = make_float2(ax, ay);
    if (insel == 0 && lane == 0) g_wsum[n] = wa;
}

// ---------------- per-layer: GEMM + bias + LeakyReLU + L2-normalize --------
// (round-3 winning config: 64 nodes/block, 16-thread groups, 4 cols, FFMA2)
#define ROWP 66
__global__ void __launch_bounds__(128) k_update(
    const float* __restrict__ W1, const float* __restrict__ b1,
    const float* __restrict__ W2, const float* __restrict__ b2,
    int l) {
    __shared__ float sA[64 * ROWP];
    __shared__ float sB[64 * ROWP];
    const float* __restrict__ Xin = (l & 1) ? g_Y : g_X;
    float* __restrict__ Yout      = (l & 1) ? g_X : g_Y;

    int tid = threadIdx.x;
    int grp = tid >> 4;
    int t16 = tid & 15;
    int node0 = blockIdx.x * 64;
    int nb = grp * 8;
    int c = t16 * 4;

    const float* W1l = W1 + l * 4096;
    const float* W2l = W2 + l * 4096;

#pragma unroll
    for (int m = 0; m < 8; m++) {
        int nl = nb + m;
        int n = node0 + nl;
        if (n < N_NODES) {
            float4 sv = *(const float4*)&g_S[(size_t)n * KDIM + c];
            float4 xv = *(const float4*)&Xin[(size_t)n * KDIM + c];
            sA[(c + 0) * ROWP + nl] = sv.x + xv.x;
            sA[(c + 1) * ROWP + nl] = sv.y + xv.y;
            sA[(c + 2) * ROWP + nl] = sv.z + xv.z;
            sA[(c + 3) * ROWP + nl] = sv.w + xv.w;
            sB[(c + 0) * ROWP + nl] = sv.x * xv.x;
            sB[(c + 1) * ROWP + nl] = sv.y * xv.y;
            sB[(c + 2) * ROWP + nl] = sv.z * xv.z;
            sB[(c + 3) * ROWP + nl] = sv.w * xv.w;
        } else {
            sA[(c + 0) * ROWP + nl] = 0.0f;
            sA[(c + 1) * ROWP + nl] = 0.0f;
            sA[(c + 2) * ROWP + nl] = 0.0f;
            sA[(c + 3) * ROWP + nl] = 0.0f;
            sB[(c + 0) * ROWP + nl] = 0.0f;
            sB[(c + 1) * ROWP + nl] = 0.0f;
            sB[(c + 2) * ROWP + nl] = 0.0f;
            sB[(c + 3) * ROWP + nl] = 0.0f;
        }
    }
    __syncwarp();

    float4 B1 = __ldg((const float4*)&b1[l * 64 + c]);
    float4 B2 = __ldg((const float4*)&b2[l * 64 + c]);

    u64 acc[4][4];
#pragma unroll
    for (int p = 0; p < 4; p++) {
        int n0 = node0 + nb + 2 * p;
        float w0 = (n0 < N_NODES) ? g_wsum[n0] : 0.0f;
        float w1 = (n0 + 1 < N_NODES) ? g_wsum[n0 + 1] : 0.0f;
        acc[p][0] = pack2((w0 + 1.0f) * B1.x + w0 * B2.x, (w1 + 1.0f) * B1.x + w1 * B2.x);
        acc[p][1] = pack2((w0 + 1.0f) * B1.y + w0 * B2.y, (w1 + 1.0f) * B1.y + w1 * B2.y);
        acc[p][2] = pack2((w0 + 1.0f) * B1.z + w0 * B2.z, (w1 + 1.0f) * B1.z + w1 * B2.z);
        acc[p][3] = pack2((w0 + 1.0f) * B1.w + w0 * B2.w, (w1 + 1.0f) * B1.w + w1 * B2.w);
    }

#pragma unroll 2
    for (int k = 0; k < 64; k++) {
        float4 w1 = __ldg((const float4*)&W1l[k * 64 + c]);
        float4 w2 = __ldg((const float4*)&W2l[k * 64 + c]);
        u64 d10 = dup2(w1.x), d11 = dup2(w1.y), d12 = dup2(w1.z), d13 = dup2(w1.w);
        u64 d20 = dup2(w2.x), d21 = dup2(w2.y), d22 = dup2(w2.z), d23 = dup2(w2.w);
        const float* ra = &sA[k * ROWP + nb];
        const float* rb = &sB[k * ROWP + nb];
#pragma unroll
        for (int p = 0; p < 4; p++) {
            u64 ap = *(const u64*)&ra[2 * p];
            u64 bp = *(const u64*)&rb[2 * p];
            fma2(acc[p][0], ap, d10);
            fma2(acc[p][1], ap, d11);
            fma2(acc[p][2], ap, d12);
            fma2(acc[p][3], ap, d13);
            fma2(acc[p][0], bp, d20);
            fma2(acc[p][1], bp, d21);
            fma2(acc[p][2], bp, d22);
            fma2(acc[p][3], bp, d23);
        }
    }

#pragma unroll
    for (int p = 0; p < 4; p++) {
        float2 y[4];
#pragma unroll
        for (int j = 0; j < 4; j++) {
            float2 v = unpack2(acc[p][j]);
            y[j].x = v.x > 0.0f ? v.x : NEG_SLOPE * v.x;
            y[j].y = v.y > 0.0f ? v.y : NEG_SLOPE * v.y;
        }
        float ssx = y[0].x * y[0].x + y[1].x * y[1].x + y[2].x * y[2].x + y[3].x * y[3].x;
        float ssy = y[0].y * y[0].y + y[1].y * y[1].y + y[2].y * y[2].y + y[3].y * y[3].y;
#pragma unroll
        for (int o = 1; o < 16; o <<= 1) {
            ssx += __shfl_xor_sync(0xffffffffu, ssx, o);
            ssy += __shfl_xor_sync(0xffffffffu, ssy, o);
        }
        float inv0 = 1.0f / fmaxf(sqrtf(ssx), EPSV);
        float inv1 = 1.0f / fmaxf(sqrtf(ssy), EPSV);
        int n0 = node0 + nb + 2 * p;
        if (n0 < N_NODES)
            *(float4*)&Yout[(size_t)n0 * KDIM + c] =
                make_float4(y[0].x * inv0, y[1].x * inv0, y[2].x * inv0, y[3].x * inv0);
        if (n0 + 1 < N_NODES)
            *(float4*)&Yout[(size_t)(n0 + 1) * KDIM + c] =
                make_float4(y[0].y * inv1, y[1].y * inv1, y[2].y * inv1, y[3].y * inv1);
    }
}

// ---------------- incremental batch dot ------------------------------------
__global__ void k_dot(const int* __restrict__ user, const int* __restrict__ pos,
                      float* __restrict__ out, int sel, int first) {
    const float* __restrict__ X = sel ? g_Y : g_X;
    int gthr = blockIdx.x * blockDim.x + threadIdx.x;
    int w = gthr >> 5;
    if (w >= BATCH) return;
    int lane = threadIdx.x & 31;
    int u  = user[w];
    int it = pos[w];
    float2 a = *(const float2*)&X[(size_t)u * KDIM + lane * 2];
    float2 b = *(const float2*)&X[((size_t)N_USERS + it) * KDIM + lane * 2];
    float d = a.x * b.x + a.y * b.y;
    d += __shfl_xor_sync(0xffffffffu, d, 16);
    d += __shfl_xor_sync(0xffffffffu, d, 8);
    d += __shfl_xor_sync(0xffffffffu, d, 4);
    d += __shfl_xor_sync(0xffffffffu, d, 2);
    d += __shfl_xor_sync(0xffffffffu, d, 1);
    if (lane == 0) out[w] = first ? d : out[w] + d;
}

// ---------------- launch ----------------------------------------------------
extern "C" void kernel_launch(void* const* d_in, const int* in_sizes, int n_in,
                              void* d_out, int out_size) {
    const float* Gu   = (const float*)d_in[0];
    const float* Gi   = (const float*)d_in[1];
    const float* W1   = (const float*)d_in[2];
    const float* b1   = (const float*)d_in[3];
    const float* W2   = (const float*)d_in[4];
    const float* b2   = (const float*)d_in[5];
    const float* ew   = (const float*)d_in[6];
    const int*   esrc = (const int*)d_in[7];
    const int*   edst = (const int*)d_in[8];
    const int*   user = (const int*)d_in[9];
    const int*   pos  = (const int*)d_in[10];
    float* out = (float*)d_out;

    const int TB = 256;
    k_init<<<(N_NODES * KDIM / 4 + TB - 1) / TB, TB>>>(Gu, Gi);
    k_hist<<<(N_EDGES / 4 + TB - 1) / TB, TB>>>(edst);
    k_part<<<SCAN_BLOCKS, 1024>>>();
    k_scanpart<<<1, 64>>>();
    k_scanfinal<<<SCAN_BLOCKS, 1024>>>();
    k_fill<<<(N_EDGES / 4 + TB - 1) / TB, TB>>>(esrc, edst, ew);

    k_dot<<<(BATCH * 32 + TB - 1) / TB, TB>>>(user, pos, out, /*sel=*/0, /*first=*/1);

    for (int l = 0; l < 3; l++) {
        int insel  = l & 1;
        int outsel = insel ^ 1;
        k_gather<<<(N_NODES * 32 + TB - 1) / TB, TB>>>(insel);
        k_update<<<(N_NODES + 63) / 64, 128>>>(W1, b1, W2, b2, l);
        k_dot<<<(BATCH * 32 + TB - 1) / TB, TB>>>(user, pos, out, outsel, /*first=*/0);
    }
}